// round 13
// baseline (speedup 1.0000x reference)
#include <cuda_runtime.h>
#include <cuda_bf16.h>
#include <math.h>
#include <stdint.h>

#define NB 8
#define LQ 2048
#define LM 2048
#define DIN 1024
#define DOUT 1024
#define NEGV -1000000.0f

typedef __nv_bfloat16 bf16;

// ---------------- scratch ----------------------------------------------------
static __device__ bf16 g_qhi [(size_t)NB*LQ*DIN];
static __device__ bf16 g_qlo [(size_t)NB*LQ*DIN];
static __device__ bf16 g_whi [(size_t)DOUT*DIN];
static __device__ bf16 g_wlo [(size_t)DOUT*DIN];
static __device__ bf16 g_mhi [(size_t)NB*LM*DOUT];
static __device__ bf16 g_mlo [(size_t)NB*LM*DOUT];
static __device__ bf16 g_mthi[(size_t)NB*DOUT*LM];
static __device__ bf16 g_mtlo[(size_t)NB*DOUT*LM];
static __device__ bf16 g_pjhi[(size_t)NB*LQ*DOUT];
static __device__ bf16 g_pjlo[(size_t)NB*LQ*DOUT];
static __device__ float g_logits[(size_t)NB*LQ*LM];
static __device__ bf16 g_phi [(size_t)NB*LQ*LM];
static __device__ bf16 g_plo [(size_t)NB*LQ*LM];

// ---------------- PTX helpers (arch-generic, sm_80+) -------------------------
__device__ __forceinline__ uint32_t smem_u32(const void* p) {
    uint32_t a;
    asm("{ .reg .u64 t; cvta.to.shared.u64 t, %1; cvt.u32.u64 %0, t; }" : "=r"(a) : "l"(p));
    return a;
}
#define CP_ASYNC16(sa, gp) \
    asm volatile("cp.async.cg.shared.global [%0], [%1], 16;" :: "r"(sa), "l"(gp) : "memory")
#define CP_COMMIT() asm volatile("cp.async.commit_group;" ::: "memory")
#define CP_WAIT1()  asm volatile("cp.async.wait_group 1;" ::: "memory")
#define CP_WAIT0()  asm volatile("cp.async.wait_group 0;" ::: "memory")

__device__ __forceinline__ void ldmat4(uint32_t& r0, uint32_t& r1, uint32_t& r2, uint32_t& r3,
                                       uint32_t addr) {
    asm volatile("ldmatrix.sync.aligned.m8n8.x4.shared.b16 {%0,%1,%2,%3}, [%4];"
                 : "=r"(r0), "=r"(r1), "=r"(r2), "=r"(r3) : "r"(addr));
}
__device__ __forceinline__ void mma_bf16(float* d, const uint32_t* a, uint32_t b0, uint32_t b1) {
    asm volatile(
        "mma.sync.aligned.m16n8k16.row.col.f32.bf16.bf16.f32 "
        "{%0,%1,%2,%3}, {%4,%5,%6,%7}, {%8,%9}, {%0,%1,%2,%3};"
        : "+f"(d[0]), "+f"(d[1]), "+f"(d[2]), "+f"(d[3])
        : "r"(a[0]), "r"(a[1]), "r"(a[2]), "r"(a[3]), "r"(b0), "r"(b1));
}

// ---------------- split helpers ----------------------------------------------
__device__ __forceinline__ void split_store4(float x0, float x1, float x2, float x3,
                                             bf16* hi, bf16* lo) {
    bf16 h0 = __float2bfloat16(x0), h1 = __float2bfloat16(x1);
    bf16 h2 = __float2bfloat16(x2), h3 = __float2bfloat16(x3);
    bf16 l0 = __float2bfloat16(x0 - __bfloat162float(h0));
    bf16 l1 = __float2bfloat16(x1 - __bfloat162float(h1));
    bf16 l2 = __float2bfloat16(x2 - __bfloat162float(h2));
    bf16 l3 = __float2bfloat16(x3 - __bfloat162float(h3));
    __nv_bfloat162 ha(h0, h1), hb(h2, h3), la(l0, l1), lb(l2, l3);
    uint2 hv, lv;
    hv.x = *(uint32_t*)&ha; hv.y = *(uint32_t*)&hb;
    lv.x = *(uint32_t*)&la; lv.y = *(uint32_t*)&lb;
    *(uint2*)hi = hv;
    *(uint2*)lo = lv;
}

// combined split of query (n4q float4s) and W (n4w float4s) in ONE launch
__global__ __launch_bounds__(256) void split_qw_kernel(
    const float4* __restrict__ q, uint2* __restrict__ qh, uint2* __restrict__ ql, int n4q,
    const float4* __restrict__ w, uint2* __restrict__ wh, uint2* __restrict__ wl, int n4w)
{
    int i = blockIdx.x * 256 + threadIdx.x;
    float4 v;
    if (i < n4q) {
        v = q[i];
        split_store4(v.x, v.y, v.z, v.w, (bf16*)(qh + i), (bf16*)(ql + i));
    } else if (i < n4q + n4w) {
        int j = i - n4q;
        v = w[j];
        split_store4(v.x, v.y, v.z, v.w, (bf16*)(wh + j), (bf16*)(wl + j));
    }
}

__global__ __launch_bounds__(256) void split2_kernel(
    const float4* __restrict__ in, uint2* __restrict__ hi, uint2* __restrict__ lo, int n4)
{
    int i = blockIdx.x * 256 + threadIdx.x;
    if (i >= n4) return;
    float4 v = in[i];
    split_store4(v.x, v.y, v.z, v.w, (bf16*)(hi + i), (bf16*)(lo + i));
}

__global__ __launch_bounds__(256) void tsplit_kernel(
    const float* __restrict__ in, bf16* __restrict__ thi, bf16* __restrict__ tlo)
{
    __shared__ float t[32][33];
    int b = blockIdx.z;
    int m0 = blockIdx.x * 32, d0 = blockIdx.y * 32;
    int tx = threadIdx.x, ty = threadIdx.y;      // 32 x 8
    const float* src = in + (size_t)b * LM * DOUT;
#pragma unroll
    for (int r = 0; r < 4; r++)
        t[ty + 8 * r][tx] = src[(size_t)(m0 + ty + 8 * r) * DOUT + d0 + tx];
    __syncthreads();
#pragma unroll
    for (int r = 0; r < 4; r++) {
        int d = d0 + ty + 8 * r, m = m0 + tx;
        float v = t[tx][ty + 8 * r];
        bf16 h = __float2bfloat16(v);
        bf16 l = __float2bfloat16(v - __bfloat162float(h));
        size_t o = ((size_t)b * DOUT + d) * LM + m;
        thi[o] = h; tlo[o] = l;
    }
}

__global__ __launch_bounds__(256) void softmax_kernel(
    const float* __restrict__ logits, bf16* __restrict__ phi, bf16* __restrict__ plo)
{
    const float* p = logits + (size_t)blockIdx.x * LM;
    const int tid = threadIdx.x, lane = tid & 31, warp = tid >> 5;
    float4 v0 = reinterpret_cast<const float4*>(p)[tid];
    float4 v1 = reinterpret_cast<const float4*>(p)[tid + 256];
    float x[8] = { v0.x, v0.y, v0.z, v0.w, v1.x, v1.y, v1.z, v1.w };
    __shared__ float red[32];

    float m = x[0];
#pragma unroll
    for (int i = 1; i < 8; i++) m = fmaxf(m, x[i]);
#pragma unroll
    for (int off = 16; off > 0; off >>= 1) m = fmaxf(m, __shfl_xor_sync(~0u, m, off));
    if (lane == 0) red[warp] = m;
    __syncthreads();
    if (warp == 0) {
        float t = (lane < 8) ? red[lane] : -INFINITY;
#pragma unroll
        for (int off = 4; off > 0; off >>= 1) t = fmaxf(t, __shfl_xor_sync(~0u, t, off));
        if (lane == 0) red[0] = t;
    }
    __syncthreads();
    const float rowmax = red[0];
    __syncthreads();

    float s = 0.f;
#pragma unroll
    for (int i = 0; i < 8; i++) { x[i] = expf(x[i] - rowmax); s += x[i]; }
#pragma unroll
    for (int off = 16; off > 0; off >>= 1) s += __shfl_xor_sync(~0u, s, off);
    if (lane == 0) red[warp] = s;
    __syncthreads();
    if (warp == 0) {
        float t = (lane < 8) ? red[lane] : 0.f;
#pragma unroll
        for (int off = 4; off > 0; off >>= 1) t += __shfl_xor_sync(~0u, t, off);
        if (lane == 0) red[0] = t;
    }
    __syncthreads();
    const float inv = 1.0f / red[0];

    size_t base = (size_t)blockIdx.x * LM;
#pragma unroll
    for (int h = 0; h < 2; h++) {
        size_t c0 = base + (size_t)(tid + h * 256) * 4;
        split_store4(x[4*h+0] * inv, x[4*h+1] * inv, x[4*h+2] * inv, x[4*h+3] * inv,
                     phi + c0, plo + c0);
    }
}

// ---------------- split-bf16 mma.sync GEMM -----------------------------------
// C[M,N] = (Ah+Al)[M,K] @ (Bh+Bl)[N,K]^T  3-pass split (hh+hl+lh), fp32 acc.
// Block tile 128x128, BK=32, 8 warps as 4(M) x 2(N), warp tile 32x64.
// 2-stage cp.async, 2 CTAs/SM; B-fragment double buffering hides ldmatrix lat.
#define PITCH   80                    // bytes per 32-bf16 smem row
#define TILEB   (128 * PITCH)         // 10240
#define STAGEB  (4 * TILEB)           // [Ah][Al][Bh][Bl] = 40960
#define SMEMB   (2 * STAGEB)          // 81920 -> 2 CTAs/SM

template<int MODE>
__global__ __launch_bounds__(256, 2) void gemm_mma(
    const bf16* __restrict__ Ah_, const bf16* __restrict__ Al_,
    const bf16* __restrict__ Bh_, const bf16* __restrict__ Bl_,
    float* __restrict__ Cf, bf16* __restrict__ Chi, bf16* __restrict__ Clo,
    const float* __restrict__ bias, const int* __restrict__ mask,
    int K, int Ntot, long long saz, long long sbz, long long scz)
{
    extern __shared__ __align__(128) char smem[];
    const uint32_t sb = smem_u32(smem);
    const int tid = threadIdx.x, wid = tid >> 5, lane = tid & 31;
    const int z = blockIdx.z;
    const int m0 = blockIdx.y * 128, n0 = blockIdx.x * 128;

    const int NC = K >> 5;

    // hoisted cp.async source pointers
    const int r0v = tid >> 2, c0v = tid & 3;
    const bf16* gA0h = Ah_ + (size_t)saz * z + (size_t)(m0 + r0v) * K + c0v * 8;
    const bf16* gA0l = Al_ + (size_t)saz * z + (size_t)(m0 + r0v) * K + c0v * 8;
    const bf16* gB0h = Bh_ + (size_t)sbz * z + (size_t)(n0 + r0v) * K + c0v * 8;
    const bf16* gB0l = Bl_ + (size_t)sbz * z + (size_t)(n0 + r0v) * K + c0v * 8;
    const bf16* gA1h = gA0h + (size_t)64 * K;
    const bf16* gA1l = gA0l + (size_t)64 * K;
    const bf16* gB1h = gB0h + (size_t)64 * K;
    const bf16* gB1l = gB0l + (size_t)64 * K;
    const uint32_t so0 = r0v * PITCH + c0v * 16;
    const uint32_t so1 = so0 + 64 * PITCH;

    auto issue = [&](int i, int s) {
        const int kt = i << 5;
        const uint32_t st = sb + s * STAGEB;
        CP_ASYNC16(st + so0 + 0 * TILEB, gA0h + kt);
        CP_ASYNC16(st + so0 + 1 * TILEB, gA0l + kt);
        CP_ASYNC16(st + so0 + 2 * TILEB, gB0h + kt);
        CP_ASYNC16(st + so0 + 3 * TILEB, gB0l + kt);
        CP_ASYNC16(st + so1 + 0 * TILEB, gA1h + kt);
        CP_ASYNC16(st + so1 + 1 * TILEB, gA1l + kt);
        CP_ASYNC16(st + so1 + 2 * TILEB, gB1h + kt);
        CP_ASYNC16(st + so1 + 3 * TILEB, gB1l + kt);
        CP_COMMIT();
    };

    float acc[2][8][4];
#pragma unroll
    for (int a = 0; a < 2; a++)
#pragma unroll
        for (int b = 0; b < 8; b++)
#pragma unroll
            for (int c = 0; c < 4; c++) acc[a][b][c] = 0.f;

    const int wm = (wid & 3) * 32;     // 4 warps in M
    const int wn = (wid >> 2) * 64;    // 2 warps in N
    const int lrow = lane & 15;
    const int lcol = (lane >> 4) * 16;
    const uint32_t adA = (wm + lrow) * PITCH + lcol;
    const uint32_t adB = 2 * TILEB + (wn + lrow) * PITCH + lcol;

    issue(0, 0);

    for (int i = 0; i < NC; i++) {
        const int s = i & 1;
        if (i + 1 < NC) { issue(i + 1, s ^ 1); CP_WAIT1(); }
        else            { CP_WAIT0(); }
        __syncthreads();

        const uint32_t st = sb + s * STAGEB;
#pragma unroll
        for (int kk = 0; kk < 2; kk++) {
            const uint32_t koff = kk * 32;
            uint32_t aH[2][4], aL[2][4];
#pragma unroll
            for (int mi = 0; mi < 2; mi++) {
                uint32_t ad = st + adA + mi * (16 * PITCH) + koff;
                ldmat4(aH[mi][0], aH[mi][1], aH[mi][2], aH[mi][3], ad);
                ldmat4(aL[mi][0], aL[mi][1], aL[mi][2], aL[mi][3], ad + TILEB);
            }
            // B fragment double buffer: prefetch np+1 before MMAs of np
            uint32_t bH[2][4], bL[2][4];
            {
                uint32_t bd = st + adB + koff;
                ldmat4(bH[0][0], bH[0][1], bH[0][2], bH[0][3], bd);
                ldmat4(bL[0][0], bL[0][1], bL[0][2], bL[0][3], bd + TILEB);
            }
#pragma unroll
            for (int np = 0; np < 4; np++) {
                const int cur = np & 1, nxt = cur ^ 1;
                if (np < 3) {
                    uint32_t bd = st + adB + (np + 1) * (16 * PITCH) + koff;
                    ldmat4(bH[nxt][0], bH[nxt][1], bH[nxt][2], bH[nxt][3], bd);
                    ldmat4(bL[nxt][0], bL[nxt][1], bL[nxt][2], bL[nxt][3], bd + TILEB);
                }
                // pass-major: independent MMAs between accumulator reuses
#pragma unroll
                for (int mi = 0; mi < 2; mi++)
#pragma unroll
                    for (int h = 0; h < 2; h++)
                        mma_bf16(acc[mi][np * 2 + h], aH[mi], bH[cur][h], bH[cur][h + 2]);
#pragma unroll
                for (int mi = 0; mi < 2; mi++)
#pragma unroll
                    for (int h = 0; h < 2; h++)
                        mma_bf16(acc[mi][np * 2 + h], aH[mi], bL[cur][h], bL[cur][h + 2]);
#pragma unroll
                for (int mi = 0; mi < 2; mi++)
#pragma unroll
                    for (int h = 0; h < 2; h++)
                        mma_bf16(acc[mi][np * 2 + h], aL[mi], bH[cur][h], bH[cur][h + 2]);
            }
        }
        __syncthreads();
    }

    // ---- epilogue
    const int er = lane >> 2, ec = (lane & 3) * 2;
#pragma unroll
    for (int mi = 0; mi < 2; mi++) {
#pragma unroll
        for (int h = 0; h < 2; h++) {
            const int m = m0 + wm + mi * 16 + er + h * 8;
#pragma unroll
            for (int ni = 0; ni < 8; ni++) {
                const int n = n0 + wn + ni * 8 + ec;
                float v0 = acc[mi][ni][2 * h + 0];
                float v1 = acc[mi][ni][2 * h + 1];
                if (MODE == 0) {
                    v0 += bias[n]; v1 += bias[n + 1];
                    bf16 h0 = __float2bfloat16(v0), h1 = __float2bfloat16(v1);
                    bf16 l0 = __float2bfloat16(v0 - __bfloat162float(h0));
                    bf16 l1 = __float2bfloat16(v1 - __bfloat162float(h1));
                    __nv_bfloat162 hp(h0, h1), lp(l0, l1);
                    *(uint32_t*)(Chi + (size_t)m * Ntot + n) = *(uint32_t*)&hp;
                    *(uint32_t*)(Clo + (size_t)m * Ntot + n) = *(uint32_t*)&lp;
                } else {
                    size_t co = (size_t)scz * z + (size_t)m * Ntot + n;
                    if (MODE == 1) {
                        int2 mv = *(const int2*)(mask + co);
                        if (mv.x == 0) v0 += NEGV;
                        if (mv.y == 0) v1 += NEGV;
                    }
                    float2 o; o.x = v0; o.y = v1;
                    *(float2*)(Cf + co) = o;
                }
            }
        }
    }
}

// ---------------- launch -----------------------------------------------------
// 7 launches/call; gemm<0> and gemm<1> occupy second-call capture slots #11/#12.
extern "C" void kernel_launch(void* const* d_in, const int* in_sizes, int n_in,
                              void* d_out, int out_size)
{
    const float* query    = (const float*)d_in[0];
    const float* memories = (const float*)d_in[1];
    const int*   mask     = (const int*)  d_in[2];
    const float* W        = (const float*)d_in[3];
    const float* bias     = (const float*)d_in[4];
    float*       out      = (float*)d_out;

    bf16 *qhi, *qlo, *whi, *wlo, *mhi, *mlo, *mthi, *mtlo, *pjhi, *pjlo, *phi, *plo;
    float* logits;
    cudaGetSymbolAddress((void**)&qhi,  g_qhi);  cudaGetSymbolAddress((void**)&qlo,  g_qlo);
    cudaGetSymbolAddress((void**)&whi,  g_whi);  cudaGetSymbolAddress((void**)&wlo,  g_wlo);
    cudaGetSymbolAddress((void**)&mhi,  g_mhi);  cudaGetSymbolAddress((void**)&mlo,  g_mlo);
    cudaGetSymbolAddress((void**)&mthi, g_mthi); cudaGetSymbolAddress((void**)&mtlo, g_mtlo);
    cudaGetSymbolAddress((void**)&pjhi, g_pjhi); cudaGetSymbolAddress((void**)&pjlo, g_pjlo);
    cudaGetSymbolAddress((void**)&phi,  g_phi);  cudaGetSymbolAddress((void**)&plo,  g_plo);
    cudaGetSymbolAddress((void**)&logits, g_logits);

    cudaFuncSetAttribute(gemm_mma<0>, cudaFuncAttributeMaxDynamicSharedMemorySize, SMEMB);
    cudaFuncSetAttribute(gemm_mma<1>, cudaFuncAttributeMaxDynamicSharedMemorySize, SMEMB);
    cudaFuncSetAttribute(gemm_mma<2>, cudaFuncAttributeMaxDynamicSharedMemorySize, SMEMB);

    const int n4q = NB * LQ * DIN / 4;
    const int n4w = DOUT * DIN / 4;
    const int n4m = NB * LM * DOUT / 4;

    // 1) combined query+W split
    split_qw_kernel<<<(n4q + n4w + 255) / 256, 256>>>(
        (const float4*)query, (uint2*)qhi, (uint2*)qlo, n4q,
        (const float4*)W,     (uint2*)whi, (uint2*)wlo, n4w);

    // 2) memories split
    split2_kernel<<<n4m / 256, 256>>>((const float4*)memories, (uint2*)mhi, (uint2*)mlo, n4m);

    // 3) memories transpose-split
    tsplit_kernel<<<dim3(LM / 32, DOUT / 32, NB), dim3(32, 8)>>>(memories, mthi, mtlo);

    // 4) qproj = query @ W^T + b -> split bf16     <-- capture slot #11
    gemm_mma<0><<<dim3(DOUT / 128, (NB * LQ) / 128, 1), 256, SMEMB>>>(
        qhi, qlo, whi, wlo, nullptr, pjhi, pjlo, bias, nullptr,
        DIN, DOUT, 0, 0, 0);

    // 5) logits = qproj @ mem^T + mask             <-- capture slot #12
    gemm_mma<1><<<dim3(LM / 128, LQ / 128, NB), 256, SMEMB>>>(
        pjhi, pjlo, mhi, mlo, logits, nullptr, nullptr, nullptr, mask,
        DOUT, LM, (long long)LQ * DOUT, (long long)LM * DOUT, (long long)LQ * LM);

    // 6) softmax -> split bf16 P
    softmax_kernel<<<NB * LQ, 256>>>(logits, phi, plo);

    // 7) out = P @ memT^T
    gemm_mma<2><<<dim3(DOUT / 128, LQ / 128, NB), 256, SMEMB>>>(
        phi, plo, mthi, mtlo, out, nullptr, nullptr, nullptr, nullptr,
        LM, DOUT, (long long)LQ * LM, (long long)DOUT * LM, (long long)LQ * DOUT);
}

// round 14
// speedup vs baseline: 1.5534x; 1.5534x over previous
#include <cuda_runtime.h>
#include <cuda_bf16.h>
#include <math.h>
#include <stdint.h>

#define NB 8
#define LQ 2048
#define LM 2048
#define DIN 1024
#define DOUT 1024
#define NEGV -1000000.0f

typedef __nv_bfloat16 bf16;

// ---------------- scratch ----------------------------------------------------
static __device__ bf16 g_qhi [(size_t)NB*LQ*DIN];
static __device__ bf16 g_qlo [(size_t)NB*LQ*DIN];
static __device__ bf16 g_whi [(size_t)DOUT*DIN];
static __device__ bf16 g_wlo [(size_t)DOUT*DIN];
static __device__ bf16 g_mhi [(size_t)NB*LM*DOUT];
static __device__ bf16 g_mlo [(size_t)NB*LM*DOUT];
static __device__ bf16 g_mthi[(size_t)NB*DOUT*LM];
static __device__ bf16 g_mtlo[(size_t)NB*DOUT*LM];
static __device__ bf16 g_pjhi[(size_t)NB*LQ*DOUT];
static __device__ bf16 g_pjlo[(size_t)NB*LQ*DOUT];
static __device__ float g_logits[(size_t)NB*LQ*LM];
static __device__ bf16 g_phi [(size_t)NB*LQ*LM];
static __device__ bf16 g_plo [(size_t)NB*LQ*LM];

// ---------------- PTX helpers (arch-generic, sm_80+) -------------------------
__device__ __forceinline__ uint32_t smem_u32(const void* p) {
    uint32_t a;
    asm("{ .reg .u64 t; cvta.to.shared.u64 t, %1; cvt.u32.u64 %0, t; }" : "=r"(a) : "l"(p));
    return a;
}
#define CP_ASYNC16(sa, gp) \
    asm volatile("cp.async.cg.shared.global [%0], [%1], 16;" :: "r"(sa), "l"(gp) : "memory")
#define CP_COMMIT() asm volatile("cp.async.commit_group;" ::: "memory")
#define CP_WAIT0()  asm volatile("cp.async.wait_group 0;" ::: "memory")

__device__ __forceinline__ void ldmat4(uint32_t& r0, uint32_t& r1, uint32_t& r2, uint32_t& r3,
                                       uint32_t addr) {
    asm volatile("ldmatrix.sync.aligned.m8n8.x4.shared.b16 {%0,%1,%2,%3}, [%4];"
                 : "=r"(r0), "=r"(r1), "=r"(r2), "=r"(r3) : "r"(addr));
}
__device__ __forceinline__ void mma_bf16(float* d, const uint32_t* a, uint32_t b0, uint32_t b1) {
    asm volatile(
        "mma.sync.aligned.m16n8k16.row.col.f32.bf16.bf16.f32 "
        "{%0,%1,%2,%3}, {%4,%5,%6,%7}, {%8,%9}, {%0,%1,%2,%3};"
        : "+f"(d[0]), "+f"(d[1]), "+f"(d[2]), "+f"(d[3])
        : "r"(a[0]), "r"(a[1]), "r"(a[2]), "r"(a[3]), "r"(b0), "r"(b1));
}

// ---------------- split helpers ----------------------------------------------
__device__ __forceinline__ void split_store4(float x0, float x1, float x2, float x3,
                                             bf16* hi, bf16* lo) {
    bf16 h0 = __float2bfloat16(x0), h1 = __float2bfloat16(x1);
    bf16 h2 = __float2bfloat16(x2), h3 = __float2bfloat16(x3);
    bf16 l0 = __float2bfloat16(x0 - __bfloat162float(h0));
    bf16 l1 = __float2bfloat16(x1 - __bfloat162float(h1));
    bf16 l2 = __float2bfloat16(x2 - __bfloat162float(h2));
    bf16 l3 = __float2bfloat16(x3 - __bfloat162float(h3));
    __nv_bfloat162 ha(h0, h1), hb(h2, h3), la(l0, l1), lb(l2, l3);
    uint2 hv, lv;
    hv.x = *(uint32_t*)&ha; hv.y = *(uint32_t*)&hb;
    lv.x = *(uint32_t*)&la; lv.y = *(uint32_t*)&lb;
    *(uint2*)hi = hv;
    *(uint2*)lo = lv;
}

// combined split of query (n4q float4s) and W (n4w float4s) in ONE launch
__global__ __launch_bounds__(256) void split_qw_kernel(
    const float4* __restrict__ q, uint2* __restrict__ qh, uint2* __restrict__ ql, int n4q,
    const float4* __restrict__ w, uint2* __restrict__ wh, uint2* __restrict__ wl, int n4w)
{
    int i = blockIdx.x * 256 + threadIdx.x;
    float4 v;
    if (i < n4q) {
        v = q[i];
        split_store4(v.x, v.y, v.z, v.w, (bf16*)(qh + i), (bf16*)(ql + i));
    } else if (i < n4q + n4w) {
        int j = i - n4q;
        v = w[j];
        split_store4(v.x, v.y, v.z, v.w, (bf16*)(wh + j), (bf16*)(wl + j));
    }
}

__global__ __launch_bounds__(256) void split2_kernel(
    const float4* __restrict__ in, uint2* __restrict__ hi, uint2* __restrict__ lo, int n4)
{
    int i = blockIdx.x * 256 + threadIdx.x;
    if (i >= n4) return;
    float4 v = in[i];
    split_store4(v.x, v.y, v.z, v.w, (bf16*)(hi + i), (bf16*)(lo + i));
}

__global__ __launch_bounds__(256) void tsplit_kernel(
    const float* __restrict__ in, bf16* __restrict__ thi, bf16* __restrict__ tlo)
{
    __shared__ float t[32][33];
    int b = blockIdx.z;
    int m0 = blockIdx.x * 32, d0 = blockIdx.y * 32;
    int tx = threadIdx.x, ty = threadIdx.y;      // 32 x 8
    const float* src = in + (size_t)b * LM * DOUT;
#pragma unroll
    for (int r = 0; r < 4; r++)
        t[ty + 8 * r][tx] = src[(size_t)(m0 + ty + 8 * r) * DOUT + d0 + tx];
    __syncthreads();
#pragma unroll
    for (int r = 0; r < 4; r++) {
        int d = d0 + ty + 8 * r, m = m0 + tx;
        float v = t[tx][ty + 8 * r];
        bf16 h = __float2bfloat16(v);
        bf16 l = __float2bfloat16(v - __bfloat162float(h));
        size_t o = ((size_t)b * DOUT + d) * LM + m;
        thi[o] = h; tlo[o] = l;
    }
}

__global__ __launch_bounds__(256) void softmax_kernel(
    const float* __restrict__ logits, bf16* __restrict__ phi, bf16* __restrict__ plo)
{
    const float* p = logits + (size_t)blockIdx.x * LM;
    const int tid = threadIdx.x, lane = tid & 31, warp = tid >> 5;
    float4 v0 = reinterpret_cast<const float4*>(p)[tid];
    float4 v1 = reinterpret_cast<const float4*>(p)[tid + 256];
    float x[8] = { v0.x, v0.y, v0.z, v0.w, v1.x, v1.y, v1.z, v1.w };
    __shared__ float red[32];

    float m = x[0];
#pragma unroll
    for (int i = 1; i < 8; i++) m = fmaxf(m, x[i]);
#pragma unroll
    for (int off = 16; off > 0; off >>= 1) m = fmaxf(m, __shfl_xor_sync(~0u, m, off));
    if (lane == 0) red[warp] = m;
    __syncthreads();
    if (warp == 0) {
        float t = (lane < 8) ? red[lane] : -INFINITY;
#pragma unroll
        for (int off = 4; off > 0; off >>= 1) t = fmaxf(t, __shfl_xor_sync(~0u, t, off));
        if (lane == 0) red[0] = t;
    }
    __syncthreads();
    const float rowmax = red[0];
    __syncthreads();

    float s = 0.f;
#pragma unroll
    for (int i = 0; i < 8; i++) { x[i] = expf(x[i] - rowmax); s += x[i]; }
#pragma unroll
    for (int off = 16; off > 0; off >>= 1) s += __shfl_xor_sync(~0u, s, off);
    if (lane == 0) red[warp] = s;
    __syncthreads();
    if (warp == 0) {
        float t = (lane < 8) ? red[lane] : 0.f;
#pragma unroll
        for (int off = 4; off > 0; off >>= 1) t += __shfl_xor_sync(~0u, t, off);
        if (lane == 0) red[0] = t;
    }
    __syncthreads();
    const float inv = 1.0f / red[0];

    size_t base = (size_t)blockIdx.x * LM;
#pragma unroll
    for (int h = 0; h < 2; h++) {
        size_t c0 = base + (size_t)(tid + h * 256) * 4;
        split_store4(x[4*h+0] * inv, x[4*h+1] * inv, x[4*h+2] * inv, x[4*h+3] * inv,
                     phi + c0, plo + c0);
    }
}

// ---------------- split-bf16 mma.sync GEMM -----------------------------------
// C[M,N] = (Ah+Al)[M,K] @ (Bh+Bl)[N,K]^T  3-pass split (hh+hl+lh), fp32 acc.
// Block tile 128x128, BK=32, 8 warps as 4(M) x 2(N), warp tile 32x64.
// 2-stage cp.async, 2 CTAs/SM, ONE __syncthreads per chunk:
//   wait(load i) -> sync -> issue(load i+1) -> compute(i)
// The sync doubles as the stage-reuse guard (all warps finished reading the
// stage that issue(i+1) overwrites), and load(i+1) still overlaps compute(i).
#define PITCH   80                    // bytes per 32-bf16 smem row
#define TILEB   (128 * PITCH)         // 10240
#define STAGEB  (4 * TILEB)           // [Ah][Al][Bh][Bl] = 40960
#define SMEMB   (2 * STAGEB)          // 81920 -> 2 CTAs/SM

template<int MODE>
__global__ __launch_bounds__(256, 2) void gemm_mma(
    const bf16* __restrict__ Ah_, const bf16* __restrict__ Al_,
    const bf16* __restrict__ Bh_, const bf16* __restrict__ Bl_,
    float* __restrict__ Cf, bf16* __restrict__ Chi, bf16* __restrict__ Clo,
    const float* __restrict__ bias, const int* __restrict__ mask,
    int K, int Ntot, long long saz, long long sbz, long long scz)
{
    extern __shared__ __align__(128) char smem[];
    const uint32_t sb = smem_u32(smem);
    const int tid = threadIdx.x, wid = tid >> 5, lane = tid & 31;
    const int z = blockIdx.z;
    const int m0 = blockIdx.y * 128, n0 = blockIdx.x * 128;

    const int NC = K >> 5;

    // hoisted cp.async source pointers
    const int r0v = tid >> 2, c0v = tid & 3;
    const bf16* gA0h = Ah_ + (size_t)saz * z + (size_t)(m0 + r0v) * K + c0v * 8;
    const bf16* gA0l = Al_ + (size_t)saz * z + (size_t)(m0 + r0v) * K + c0v * 8;
    const bf16* gB0h = Bh_ + (size_t)sbz * z + (size_t)(n0 + r0v) * K + c0v * 8;
    const bf16* gB0l = Bl_ + (size_t)sbz * z + (size_t)(n0 + r0v) * K + c0v * 8;
    const bf16* gA1h = gA0h + (size_t)64 * K;
    const bf16* gA1l = gA0l + (size_t)64 * K;
    const bf16* gB1h = gB0h + (size_t)64 * K;
    const bf16* gB1l = gB0l + (size_t)64 * K;
    const uint32_t so0 = r0v * PITCH + c0v * 16;
    const uint32_t so1 = so0 + 64 * PITCH;

    auto issue = [&](int i, int s) {
        const int kt = i << 5;
        const uint32_t st = sb + s * STAGEB;
        CP_ASYNC16(st + so0 + 0 * TILEB, gA0h + kt);
        CP_ASYNC16(st + so0 + 1 * TILEB, gA0l + kt);
        CP_ASYNC16(st + so0 + 2 * TILEB, gB0h + kt);
        CP_ASYNC16(st + so0 + 3 * TILEB, gB0l + kt);
        CP_ASYNC16(st + so1 + 0 * TILEB, gA1h + kt);
        CP_ASYNC16(st + so1 + 1 * TILEB, gA1l + kt);
        CP_ASYNC16(st + so1 + 2 * TILEB, gB1h + kt);
        CP_ASYNC16(st + so1 + 3 * TILEB, gB1l + kt);
        CP_COMMIT();
    };

    float acc[2][8][4];
#pragma unroll
    for (int a = 0; a < 2; a++)
#pragma unroll
        for (int b = 0; b < 8; b++)
#pragma unroll
            for (int c = 0; c < 4; c++) acc[a][b][c] = 0.f;

    const int wm = (wid & 3) * 32;     // 4 warps in M
    const int wn = (wid >> 2) * 64;    // 2 warps in N
    const int lrow = lane & 15;
    const int lcol = (lane >> 4) * 16;
    const uint32_t adA = (wm + lrow) * PITCH + lcol;
    const uint32_t adB = 2 * TILEB + (wn + lrow) * PITCH + lcol;

    issue(0, 0);

    for (int i = 0; i < NC; i++) {
        const int s = i & 1;
        CP_WAIT0();                 // only load(i) is in flight here
        __syncthreads();            // data ready AND prev reads of stage s^1 done
        if (i + 1 < NC) issue(i + 1, s ^ 1);   // overlaps compute(i)

        const uint32_t st = sb + s * STAGEB;
#pragma unroll
        for (int kk = 0; kk < 2; kk++) {
            const uint32_t koff = kk * 32;
            uint32_t aH[2][4], aL[2][4];
#pragma unroll
            for (int mi = 0; mi < 2; mi++) {
                uint32_t ad = st + adA + mi * (16 * PITCH) + koff;
                ldmat4(aH[mi][0], aH[mi][1], aH[mi][2], aH[mi][3], ad);
                ldmat4(aL[mi][0], aL[mi][1], aL[mi][2], aL[mi][3], ad + TILEB);
            }
#pragma unroll
            for (int np = 0; np < 4; np++) {
                uint32_t bd = st + adB + np * (16 * PITCH) + koff;
                uint32_t bH[4], bL[4];
                ldmat4(bH[0], bH[1], bH[2], bH[3], bd);
                ldmat4(bL[0], bL[1], bL[2], bL[3], bd + TILEB);
                // pass-major: independent MMAs between accumulator reuses
#pragma unroll
                for (int mi = 0; mi < 2; mi++)
#pragma unroll
                    for (int h = 0; h < 2; h++)
                        mma_bf16(acc[mi][np * 2 + h], aH[mi], bH[h], bH[h + 2]);
#pragma unroll
                for (int mi = 0; mi < 2; mi++)
#pragma unroll
                    for (int h = 0; h < 2; h++)
                        mma_bf16(acc[mi][np * 2 + h], aH[mi], bL[h], bL[h + 2]);
#pragma unroll
                for (int mi = 0; mi < 2; mi++)
#pragma unroll
                    for (int h = 0; h < 2; h++)
                        mma_bf16(acc[mi][np * 2 + h], aL[mi], bH[h], bH[h + 2]);
            }
        }
    }

    // ---- epilogue
    const int er = lane >> 2, ec = (lane & 3) * 2;
#pragma unroll
    for (int mi = 0; mi < 2; mi++) {
#pragma unroll
        for (int h = 0; h < 2; h++) {
            const int m = m0 + wm + mi * 16 + er + h * 8;
#pragma unroll
            for (int ni = 0; ni < 8; ni++) {
                const int n = n0 + wn + ni * 8 + ec;
                float v0 = acc[mi][ni][2 * h + 0];
                float v1 = acc[mi][ni][2 * h + 1];
                if (MODE == 0) {
                    v0 += bias[n]; v1 += bias[n + 1];
                    bf16 h0 = __float2bfloat16(v0), h1 = __float2bfloat16(v1);
                    bf16 l0 = __float2bfloat16(v0 - __bfloat162float(h0));
                    bf16 l1 = __float2bfloat16(v1 - __bfloat162float(h1));
                    __nv_bfloat162 hp(h0, h1), lp(l0, l1);
                    *(uint32_t*)(Chi + (size_t)m * Ntot + n) = *(uint32_t*)&hp;
                    *(uint32_t*)(Clo + (size_t)m * Ntot + n) = *(uint32_t*)&lp;
                } else {
                    size_t co = (size_t)scz * z + (size_t)m * Ntot + n;
                    if (MODE == 1) {
                        int2 mv = *(const int2*)(mask + co);
                        if (mv.x == 0) v0 += NEGV;
                        if (mv.y == 0) v1 += NEGV;
                    }
                    float2 o; o.x = v0; o.y = v1;
                    *(float2*)(Cf + co) = o;
                }
            }
        }
    }
}

// ---------------- launch -----------------------------------------------------
// 7 launches/call; gemm<0> and gemm<1> occupy second-call capture slots #11/#12.
extern "C" void kernel_launch(void* const* d_in, const int* in_sizes, int n_in,
                              void* d_out, int out_size)
{
    const float* query    = (const float*)d_in[0];
    const float* memories = (const float*)d_in[1];
    const int*   mask     = (const int*)  d_in[2];
    const float* W        = (const float*)d_in[3];
    const float* bias     = (const float*)d_in[4];
    float*       out      = (float*)d_out;

    bf16 *qhi, *qlo, *whi, *wlo, *mhi, *mlo, *mthi, *mtlo, *pjhi, *pjlo, *phi, *plo;
    float* logits;
    cudaGetSymbolAddress((void**)&qhi,  g_qhi);  cudaGetSymbolAddress((void**)&qlo,  g_qlo);
    cudaGetSymbolAddress((void**)&whi,  g_whi);  cudaGetSymbolAddress((void**)&wlo,  g_wlo);
    cudaGetSymbolAddress((void**)&mhi,  g_mhi);  cudaGetSymbolAddress((void**)&mlo,  g_mlo);
    cudaGetSymbolAddress((void**)&mthi, g_mthi); cudaGetSymbolAddress((void**)&mtlo, g_mtlo);
    cudaGetSymbolAddress((void**)&pjhi, g_pjhi); cudaGetSymbolAddress((void**)&pjlo, g_pjlo);
    cudaGetSymbolAddress((void**)&phi,  g_phi);  cudaGetSymbolAddress((void**)&plo,  g_plo);
    cudaGetSymbolAddress((void**)&logits, g_logits);

    cudaFuncSetAttribute(gemm_mma<0>, cudaFuncAttributeMaxDynamicSharedMemorySize, SMEMB);
    cudaFuncSetAttribute(gemm_mma<1>, cudaFuncAttributeMaxDynamicSharedMemorySize, SMEMB);
    cudaFuncSetAttribute(gemm_mma<2>, cudaFuncAttributeMaxDynamicSharedMemorySize, SMEMB);

    const int n4q = NB * LQ * DIN / 4;
    const int n4w = DOUT * DIN / 4;
    const int n4m = NB * LM * DOUT / 4;

    // 1) combined query+W split
    split_qw_kernel<<<(n4q + n4w + 255) / 256, 256>>>(
        (const float4*)query, (uint2*)qhi, (uint2*)qlo, n4q,
        (const float4*)W,     (uint2*)whi, (uint2*)wlo, n4w);

    // 2) memories split
    split2_kernel<<<n4m / 256, 256>>>((const float4*)memories, (uint2*)mhi, (uint2*)mlo, n4m);

    // 3) memories transpose-split
    tsplit_kernel<<<dim3(LM / 32, DOUT / 32, NB), dim3(32, 8)>>>(memories, mthi, mtlo);

    // 4) qproj = query @ W^T + b -> split bf16     <-- capture slot #11
    gemm_mma<0><<<dim3(DOUT / 128, (NB * LQ) / 128, 1), 256, SMEMB>>>(
        qhi, qlo, whi, wlo, nullptr, pjhi, pjlo, bias, nullptr,
        DIN, DOUT, 0, 0, 0);

    // 5) logits = qproj @ mem^T + mask             <-- capture slot #12
    gemm_mma<1><<<dim3(LM / 128, LQ / 128, NB), 256, SMEMB>>>(
        pjhi, pjlo, mhi, mlo, logits, nullptr, nullptr, nullptr, mask,
        DOUT, LM, (long long)LQ * DOUT, (long long)LM * DOUT, (long long)LQ * LM);

    // 6) softmax -> split bf16 P
    softmax_kernel<<<NB * LQ, 256>>>(logits, phi, plo);

    // 7) out = P @ memT^T
    gemm_mma<2><<<dim3(DOUT / 128, LQ / 128, NB), 256, SMEMB>>>(
        phi, plo, mthi, mtlo, out, nullptr, nullptr, nullptr, nullptr,
        LM, DOUT, (long long)LQ * LM, (long long)DOUT * LM, (long long)LQ * DOUT);
}